// round 11
// baseline (speedup 1.0000x reference)
#include <cuda_runtime.h>
#include <cuda_bf16.h>
#include <math.h>
#include <stdint.h>

// Problem constants: N=50000 nodes, E=800000 edges, F=64, HID=64, OUT=32
#define MAXN 50176      // 49*1024, divisible by 4
#define MAXE 800008     // +8 pad: prop prefetches one past segment end
#define NBZ 49          // zero/scan blocks (1024 elems each)

// ---------- device scratch (no allocations allowed) ----------
__device__ __align__(16) float g_deg[MAXN];
__device__ __align__(16) float g_dinv[MAXN];
__device__ __align__(16) int   g_count[MAXN];
__device__ __align__(16) int   g_cursor[MAXN];
__device__ __align__(16) int   g_offs[MAXN];
__device__ __align__(16) int   g_bpref[64];
__device__ __align__(16) int2  g_pair[MAXE];   // (src, bitcast(coef))
__device__ __align__(16) float g_px[MAXN * 64];
__device__ int g_is64;     // 1 if edge_index is int64, 0 if int32
__device__ int g_done_a;   // zero-phase completion counter (reset by k_fused)
__device__ int g_done_b;   // scan-phase completion counter (reset by k_fused)

__device__ __forceinline__ int load_idx(const void* ei, int pos) {
    if (g_is64) return (int)((const long long*)ei)[pos];
    return ((const int*)ei)[pos];
}
__device__ __forceinline__ int clampi(int v, int n) {
    return ((unsigned)v < (unsigned)n) ? v : 0;
}

// ---------- packed f32x2 helpers ----------
__device__ __forceinline__ void ffma2(unsigned long long& d, unsigned long long a,
                                      unsigned long long b) {
    asm("fma.rn.f32x2 %0, %1, %2, %0;" : "+l"(d) : "l"(a), "l"(b));
}
__device__ __forceinline__ unsigned long long dupf(float f) {
    unsigned long long r;
    asm("mov.b64 %0, {%1, %1};" : "=l"(r) : "f"(f));
    return r;
}
__device__ __forceinline__ unsigned long long packf(float lo, float hi) {
    unsigned long long r;
    asm("mov.b64 %0, {%1, %2};" : "=l"(r) : "f"(lo), "f"(hi));
    return r;
}
__device__ __forceinline__ void unpackf(unsigned long long v, float& lo, float& hi) {
    asm("mov.b64 {%0, %1}, %2;" : "=f"(lo), "=f"(hi) : "l"(v));
}

// ---------- mma.sync helpers (sm_80+ path, works at compute_103) ----------
__device__ __forceinline__ uint32_t smem_u32(const void* p) {
    uint32_t a;
    asm("{ .reg .u64 t; cvta.to.shared.u64 t, %1; cvt.u32.u64 %0, t; }" : "=r"(a) : "l"(p));
    return a;
}
__device__ __forceinline__ void ldsm4(uint32_t* r, uint32_t a) {
    asm volatile("ldmatrix.sync.aligned.m8n8.x4.shared.b16 {%0,%1,%2,%3}, [%4];"
        : "=r"(r[0]), "=r"(r[1]), "=r"(r[2]), "=r"(r[3]) : "r"(a));
}
__device__ __forceinline__ void ldsm4t(uint32_t* r, uint32_t a) {
    asm volatile("ldmatrix.sync.aligned.m8n8.x4.trans.shared.b16 {%0,%1,%2,%3}, [%4];"
        : "=r"(r[0]), "=r"(r[1]), "=r"(r[2]), "=r"(r[3]) : "r"(a));
}
__device__ __forceinline__ void mma16816(float* d, const uint32_t* a, uint32_t b0, uint32_t b1) {
    asm volatile("mma.sync.aligned.m16n8k16.row.col.f32.bf16.bf16.f32 "
        "{%0,%1,%2,%3}, {%4,%5,%6,%7}, {%8,%9}, {%0,%1,%2,%3};"
        : "+f"(d[0]), "+f"(d[1]), "+f"(d[2]), "+f"(d[3])
        : "r"(a[0]), "r"(a[1]), "r"(a[2]), "r"(a[3]), "r"(b0), "r"(b1));
}

// ---------- A: zero + dtype detect (blocks 0..48) | edge1 (blocks 49..) ----------
__global__ void k_zero_edge1(const void* __restrict__ ei, const float* __restrict__ ew,
                             int e, int n) {
    int bid = blockIdx.x, tid = threadIdx.x;
    if (bid < NBZ) {
        int i = bid * 256 + tid;
        int4 z = make_int4(0, 0, 0, 0);
        reinterpret_cast<int4*>(g_deg)[i] = z;
        reinterpret_cast<int4*>(g_count)[i] = z;
        reinterpret_cast<int4*>(g_cursor)[i] = z;
        if (bid == 0) {
            if (tid < 64) g_bpref[tid] = 0;
            __shared__ int any;
            if (tid == 0) any = 0;
            __syncthreads();
            if (tid < 128 && ((const int*)ei)[2 * tid + 1] != 0) atomicOr(&any, 1);
            __syncthreads();
            if (tid == 0) g_is64 = (any == 0) ? 1 : 0;
        }
        __syncthreads();
        __threadfence();
        if (tid == 0) atomicAdd(&g_done_a, 1);
    } else {
        if (tid == 0) { while (atomicAdd(&g_done_a, 0) < NBZ) {} }
        __syncthreads();
        __threadfence();
        int i = (bid - NBZ) * 256 + tid;
        if (i < e) {
            int s = clampi(load_idx(ei, i), n);
            int d = clampi(load_idx(ei, e + i), n);
            atomicAdd(&g_deg[s], ew[i]);
            atomicAdd(&g_count[d], 1);
        }
    }
}

// ---------- B: dinv + scan (blocks 0..48) | edge2 bucket fill (blocks 49..) ----------
__global__ void k_scan_edge2(const void* __restrict__ ei, const float* __restrict__ ew,
                             int e, int n) {
    int bid = blockIdx.x, tid = threadIdx.x;
    if (bid < NBZ) {
        __shared__ int sh[256];
        __shared__ int s_total;
        int4 c4 = reinterpret_cast<const int4*>(g_count)[bid * 256 + tid];
        float4 d4 = reinterpret_cast<const float4*>(g_deg)[bid * 256 + tid];
        float4 dv;
        dv.x = (d4.x > 0.f) ? rsqrtf(d4.x) : 0.f;
        dv.y = (d4.y > 0.f) ? rsqrtf(d4.y) : 0.f;
        dv.z = (d4.z > 0.f) ? rsqrtf(d4.z) : 0.f;
        dv.w = (d4.w > 0.f) ? rsqrtf(d4.w) : 0.f;
        reinterpret_cast<float4*>(g_dinv)[bid * 256 + tid] = dv;
        int tsum = c4.x + c4.y + c4.z + c4.w;
        sh[tid] = tsum;
        __syncthreads();
        for (int d = 1; d < 256; d <<= 1) {
            int add = (tid >= d) ? sh[tid - d] : 0;
            __syncthreads();
            sh[tid] += add;
            __syncthreads();
        }
        int excl = sh[tid] - tsum;
        int4 o4;
        o4.x = excl;
        o4.y = excl + c4.x;
        o4.z = excl + c4.x + c4.y;
        o4.w = excl + c4.x + c4.y + c4.z;
        reinterpret_cast<int4*>(g_offs)[bid * 256 + tid] = o4;
        if (tid == 255) s_total = sh[255];
        __syncthreads();
        int b2 = bid + 1 + tid;
        if (tid < 64 && b2 < NBZ) atomicAdd(&g_bpref[b2], s_total);
        __threadfence();
        __syncthreads();
        if (tid == 0) atomicAdd(&g_done_b, 1);
    } else {
        if (tid == 0) { while (atomicAdd(&g_done_b, 0) < NBZ) {} }
        __syncthreads();
        __threadfence();
        int i = (bid - NBZ) * 256 + tid;
        if (i < e) {
            int s = clampi(load_idx(ei, i), n);
            int d = clampi(load_idx(ei, e + i), n);
            int pos = g_offs[d] + g_bpref[d >> 10] + atomicAdd(&g_cursor[d], 1);
            pos = clampi(pos, e);
            float c = -g_dinv[s] * ew[i] * g_dinv[d];
            g_pair[pos] = make_int2(s, __float_as_int(c));
        }
    }
}

// ---------- K3: propagation px[dst] = sum coef * x[src], one warp per dst ----------
__global__ void k_prop(const float* __restrict__ x, int n) {
    int gw = (blockIdx.x * blockDim.x + threadIdx.x) >> 5;
    int lane = threadIdx.x & 31;
    if (gw >= n) return;
    int start = g_offs[gw] + g_bpref[gw >> 10];
    int m = g_count[gw];
    float a0 = 0.f, a1 = 0.f;
    if (m > 0) {
        int2 sc = __ldg(&g_pair[start]);
        for (int j = 0; j < m; j++) {
            int2 nxt = __ldg(&g_pair[start + j + 1]);
            const float* xr = x + (size_t)sc.x * 64;
            float c = __int_as_float(sc.y);
            a0 = fmaf(c, __ldg(&xr[lane]), a0);
            a1 = fmaf(c, __ldg(&xr[lane + 32]), a1);
            sc = nxt;
        }
    }
    g_px[(size_t)gw * 64 + lane] = a0;
    g_px[(size_t)gw * 64 + 32 + lane] = a1;
}

// ---------- K4: mma.sync fused kernel ----------
// 128 nodes/block, 256 threads (8 warps). D[128x128] = [x|px] @ Wcomb, bf16 hi/lo x3.
// Warp w computes D rows 16w..16w+15, all 128 cols.
#define TMF 128
#define ST 136   // smem tile row stride in bf16 (conflict-free LDSM phases)
#define TILE_B (128 * ST * 2)          // 34816 B per tile
#define SM_AH 0
#define SM_AL (SM_AH + TILE_B)
#define SM_BH (SM_AL + TILE_B)
#define SM_BL (SM_BH + TILE_B)
#define SM_U  SM_BH                    // overlay: U (128*65*4 = 33280 B) over dead BH
#define SM_WL (SM_BL + TILE_B)         // 64*32 fp32 = 8192 B
#define SM_BLIN (SM_WL + 8192)         // 128 B
#define SM_BIAS (SM_BLIN + 128)        // 512 B
#define SM_TOT  (SM_BIAS + 512)        // 148096 B

__global__ __launch_bounds__(256, 1) void k_fused(
    const float* __restrict__ x,
    const float* __restrict__ Wxz0, const float* __restrict__ Wxz1,
    const float* __restrict__ bxz,  const float* __restrict__ bhz,
    const float* __restrict__ Wxh0, const float* __restrict__ Wxh1,
    const float* __restrict__ bxh,  const float* __restrict__ bhh,
    const float* __restrict__ Wlin, const float* __restrict__ blin,
    float* __restrict__ out, int n)
{
    extern __shared__ __align__(16) char smem[];
    uint32_t sbase = smem_u32(smem);
    float* sU    = (float*)(smem + SM_U);
    float* sWl   = (float*)(smem + SM_WL);
    float* sBlin = (float*)(smem + SM_BLIN);
    float* sBias = (float*)(smem + SM_BIAS);

    int tid = threadIdx.x;
    int wid = tid >> 5, lane = tid & 31;
    int node0 = blockIdx.x * TMF;

    if (blockIdx.x == 0 && tid == 0) { g_done_a = 0; g_done_b = 0; }  // replay reset

    // ---- fill A tiles (bf16 hi/lo): row=node, col=[x|px], padded row-major ----
    for (int idx = tid; idx < TMF * 128; idx += 256) {
        int row = idx >> 7, col = idx & 127;
        int node = node0 + row;
        float a = 0.f;
        if (node < n) a = (col < 64) ? x[(size_t)node * 64 + col]
                                     : g_px[(size_t)node * 64 + (col - 64)];
        __nv_bfloat16 h = __float2bfloat16(a);
        __nv_bfloat16 l = __float2bfloat16(a - __bfloat162float(h));
        uint32_t off = (uint32_t)(row * ST + col) * 2;
        *reinterpret_cast<__nv_bfloat16*>(smem + SM_AH + off) = h;
        *reinterpret_cast<__nv_bfloat16*>(smem + SM_AL + off) = l;
    }
    // ---- fill B tiles (bf16 hi/lo): row=k, col=o; B[k][o] = Wcomb[k][o] ----
    for (int idx = tid; idx < 128 * 128; idx += 256) {
        int k = idx >> 7, o = idx & 127;
        float v;
        if (k < 64) v = (o < 64) ? Wxz0[k * 64 + o] : Wxh0[k * 64 + (o - 64)];
        else        v = (o < 64) ? Wxz1[(k - 64) * 64 + o] : Wxh1[(k - 64) * 64 + (o - 64)];
        __nv_bfloat16 h = __float2bfloat16(v);
        __nv_bfloat16 l = __float2bfloat16(v - __bfloat162float(h));
        uint32_t off = (uint32_t)(k * ST + o) * 2;
        *reinterpret_cast<__nv_bfloat16*>(smem + SM_BH + off) = h;
        *reinterpret_cast<__nv_bfloat16*>(smem + SM_BL + off) = l;
    }
    for (int idx = tid; idx < 2048; idx += 256) sWl[idx] = Wlin[idx];
    if (tid < 128) sBias[tid] = (tid < 64) ? (bxz[tid] + bhz[tid]) : (bxh[tid - 64] + bhh[tid - 64]);
    if (tid < 32) sBlin[tid] = blin[tid];
    __syncthreads();

    // ---- stage A: warp-level mma, rows 16w..16w+15, 16 n-tiles, K=128 ----
    int qr = lane >> 2;          // fragment row offset (0..7)
    int qc = (lane & 3) * 2;     // fragment col offset (0,2,4,6)
    int r0 = wid * 16;
    float acc[16][4];
#pragma unroll
    for (int nt = 0; nt < 16; nt++) {
        float b0 = sBias[nt * 8 + qc], b1 = sBias[nt * 8 + qc + 1];
        acc[nt][0] = b0; acc[nt][1] = b1; acc[nt][2] = b0; acc[nt][3] = b1;
    }
    // ldmatrix lane address pattern (same formula for A and B-trans):
    // row = base_row + (lane&15), col = base_col + ((lane>>4)<<3)
    int lr = lane & 15, lc = (lane >> 4) << 3;
#pragma unroll
    for (int ks = 0; ks < 8; ks++) {
        int k0 = ks * 16;
        uint32_t ah[4], al[4];
        uint32_t aaddr = sbase + SM_AH + (uint32_t)((r0 + lr) * ST + k0 + lc) * 2;
        ldsm4(ah, aaddr);
        ldsm4(al, aaddr + (SM_AL - SM_AH));
#pragma unroll
        for (int np = 0; np < 8; np++) {
            int n0 = np * 16;
            uint32_t baddr = sbase + SM_BH + (uint32_t)((k0 + lr) * ST + n0 + lc) * 2;
            uint32_t bh[4], bl[4];
            ldsm4t(bh, baddr);
            ldsm4t(bl, baddr + (SM_BL - SM_BH));
            mma16816(acc[2 * np],     ah, bh[0], bh[1]);
            mma16816(acc[2 * np],     ah, bl[0], bl[1]);
            mma16816(acc[2 * np],     al, bh[0], bh[1]);
            mma16816(acc[2 * np + 1], ah, bh[2], bh[3]);
            mma16816(acc[2 * np + 1], ah, bl[2], bl[3]);
            mma16816(acc[2 * np + 1], al, bh[2], bh[3]);
        }
    }
    __syncthreads();   // B tiles dead; safe to overlay U

    // ---- gate in registers: z = acc[nt] (cols c), h = acc[nt+8] (cols c+64) ----
    {
        int r = r0 + qr;
#pragma unroll
        for (int nt = 0; nt < 8; nt++) {
            int c = nt * 8 + qc;
#pragma unroll
            for (int j = 0; j < 4; j++) {
                float zp = acc[nt][j];
                float hp = acc[nt + 8][j];
                float z = 1.f / (1.f + __expf(-zp));
                float u = (1.f - z) * tanhf(hp);
                int rr = r + ((j >> 1) << 3);       // j=2,3 -> row+8
                int cc = c + (j & 1);
                sU[rr * 65 + cc] = u;
            }
        }
    }
    __syncthreads();

    // ---- stage B: U(128x64) @ Wlin(64x32) + blin, f32x2; row-normalize ----
    {
        int node = tid >> 1;           // 0..127
        int q = tid & 1;               // out half: outs q*16 .. q*16+15
        int ob = q * 16;
        unsigned long long a[8];
#pragma unroll
        for (int m2 = 0; m2 < 8; m2++) a[m2] = packf(sBlin[ob + 2 * m2], sBlin[ob + 2 * m2 + 1]);
#pragma unroll 4
        for (int k = 0; k < 64; k++) {
            unsigned long long up = dupf(sU[node * 65 + k]);
            ulonglong2 w0 = *reinterpret_cast<const ulonglong2*>(&sWl[k * 32 + ob]);
            ulonglong2 w1 = *reinterpret_cast<const ulonglong2*>(&sWl[k * 32 + ob + 4]);
            ulonglong2 w2 = *reinterpret_cast<const ulonglong2*>(&sWl[k * 32 + ob + 8]);
            ulonglong2 w3 = *reinterpret_cast<const ulonglong2*>(&sWl[k * 32 + ob + 12]);
            ffma2(a[0], up, w0.x); ffma2(a[1], up, w0.y);
            ffma2(a[2], up, w1.x); ffma2(a[3], up, w1.y);
            ffma2(a[4], up, w2.x); ffma2(a[5], up, w2.y);
            ffma2(a[6], up, w3.x); ffma2(a[7], up, w3.y);
        }
        float o[16];
#pragma unroll
        for (int m2 = 0; m2 < 8; m2++) unpackf(a[m2], o[2 * m2], o[2 * m2 + 1]);
        float ss = 0.f;
#pragma unroll
        for (int m2 = 0; m2 < 16; m2++) ss = fmaf(o[m2], o[m2], ss);
        ss += __shfl_xor_sync(0xffffffffu, ss, 1);   // partner holds other 16 outs
        float scale = 1.f / fmaxf(sqrtf(ss), 1e-12f);
        int gnode = node0 + node;
        if (gnode < n) {
#pragma unroll
            for (int v = 0; v < 4; v++) {
                float4 o4 = make_float4(o[4 * v] * scale, o[4 * v + 1] * scale,
                                        o[4 * v + 2] * scale, o[4 * v + 3] * scale);
                reinterpret_cast<float4*>(out)[(size_t)gnode * 8 + q * 4 + v] = o4;
            }
        }
    }
}

extern "C" void kernel_launch(void* const* d_in, const int* in_sizes, int n_in,
                              void* d_out, int out_size) {
    const float* x    = (const float*)d_in[0];
    const void*  ei   = d_in[1];
    const float* ew   = (const float*)d_in[2];
    const float* Wxz0 = (const float*)d_in[3];
    const float* Wxz1 = (const float*)d_in[4];
    const float* bxz  = (const float*)d_in[5];
    const float* bhz  = (const float*)d_in[8];
    const float* Wxh0 = (const float*)d_in[15];
    const float* Wxh1 = (const float*)d_in[16];
    const float* bxh  = (const float*)d_in[17];
    const float* bhh  = (const float*)d_in[20];
    const float* Wlin = (const float*)d_in[21];
    const float* blin = (const float*)d_in[22];
    float* out = (float*)d_out;

    int n = in_sizes[0] / 64;   // 50000
    int e = in_sizes[2];        // 800000

    static int s_attr_done = 0;
    if (!s_attr_done) {
        cudaFuncSetAttribute(k_fused, cudaFuncAttributeMaxDynamicSharedMemorySize, SM_TOT);
        s_attr_done = 1;
    }

    int nbE = (e + 255) / 256;

    k_zero_edge1<<<NBZ + nbE, 256>>>(ei, ew, e, n);     // #1
    k_scan_edge2<<<NBZ + nbE, 256>>>(ei, ew, e, n);     // #2
    k_prop<<<(n * 32 + 255) / 256, 256>>>(x, n);        // #3
    k_fused<<<(n + TMF - 1) / TMF, 256, SM_TOT>>>(      // #4  <- ncu window
        x, Wxz0, Wxz1, bxz, bhz, Wxh0, Wxh1, bxh, bhh, Wlin, blin, out, n);
}

// round 12
// speedup vs baseline: 1.0954x; 1.0954x over previous
#include <cuda_runtime.h>
#include <cuda_bf16.h>
#include <math.h>
#include <stdint.h>

// Problem constants: N=50000 nodes, E=800000 edges, F=64, HID=64, OUT=32
#define MAXN 50176      // 49*1024, divisible by 4
#define MAXE 800008     // +8 pad: prop prefetches one past segment end
#define NBZ 49          // zero/scan blocks (1024 elems each)
#define NWB 64          // weight-conversion blocks appended to k_zero_edge1

#define ST 136          // bf16 tile row stride (as verified in R11)
#define TILE_B (128 * ST * 2)   // 34816 B per bf16 tile

// ---------- device scratch (no allocations allowed) ----------
__device__ __align__(16) float g_deg[MAXN];
__device__ __align__(16) float g_dinv[MAXN];
__device__ __align__(16) int   g_count[MAXN];
__device__ __align__(16) int   g_cursor[MAXN];
__device__ __align__(16) int   g_offs[MAXN];
__device__ __align__(16) int   g_bpref[64];
__device__ __align__(16) int2  g_pair[MAXE];   // (src, bitcast(coef))
__device__ __align__(16) float g_px[MAXN * 64];
__device__ __align__(16) __nv_bfloat16 g_wbh[128 * ST];  // weight tile hi (ldsm layout)
__device__ __align__(16) __nv_bfloat16 g_wbl[128 * ST];  // weight tile lo
__device__ int g_is64;
__device__ int g_done_a;
__device__ int g_done_b;

__device__ __forceinline__ int load_idx(const void* ei, int pos) {
    if (g_is64) return (int)((const long long*)ei)[pos];
    return ((const int*)ei)[pos];
}
__device__ __forceinline__ int clampi(int v, int n) {
    return ((unsigned)v < (unsigned)n) ? v : 0;
}

// ---------- packed f32x2 helpers ----------
__device__ __forceinline__ void ffma2(unsigned long long& d, unsigned long long a,
                                      unsigned long long b) {
    asm("fma.rn.f32x2 %0, %1, %2, %0;" : "+l"(d) : "l"(a), "l"(b));
}
__device__ __forceinline__ unsigned long long dupf(float f) {
    unsigned long long r;
    asm("mov.b64 %0, {%1, %1};" : "=l"(r) : "f"(f));
    return r;
}
__device__ __forceinline__ unsigned long long packf(float lo, float hi) {
    unsigned long long r;
    asm("mov.b64 %0, {%1, %2};" : "=l"(r) : "f"(lo), "f"(hi));
    return r;
}
__device__ __forceinline__ void unpackf(unsigned long long v, float& lo, float& hi) {
    asm("mov.b64 {%0, %1}, %2;" : "=f"(lo), "=f"(hi) : "l"(v));
}

// ---------- mma.sync helpers ----------
__device__ __forceinline__ uint32_t smem_u32(const void* p) {
    uint32_t a;
    asm("{ .reg .u64 t; cvta.to.shared.u64 t, %1; cvt.u32.u64 %0, t; }" : "=r"(a) : "l"(p));
    return a;
}
__device__ __forceinline__ void ldsm4(uint32_t* r, uint32_t a) {
    asm volatile("ldmatrix.sync.aligned.m8n8.x4.shared.b16 {%0,%1,%2,%3}, [%4];"
        : "=r"(r[0]), "=r"(r[1]), "=r"(r[2]), "=r"(r[3]) : "r"(a));
}
__device__ __forceinline__ void ldsm4t(uint32_t* r, uint32_t a) {
    asm volatile("ldmatrix.sync.aligned.m8n8.x4.trans.shared.b16 {%0,%1,%2,%3}, [%4];"
        : "=r"(r[0]), "=r"(r[1]), "=r"(r[2]), "=r"(r[3]) : "r"(a));
}
__device__ __forceinline__ void mma16816(float* d, const uint32_t* a, uint32_t b0, uint32_t b1) {
    asm volatile("mma.sync.aligned.m16n8k16.row.col.f32.bf16.bf16.f32 "
        "{%0,%1,%2,%3}, {%4,%5,%6,%7}, {%8,%9}, {%0,%1,%2,%3};"
        : "+f"(d[0]), "+f"(d[1]), "+f"(d[2]), "+f"(d[3])
        : "r"(a[0]), "r"(a[1]), "r"(a[2]), "r"(a[3]), "r"(b0), "r"(b1));
}

// ---------- A: zero+detect | edge1 | weight bf16 conversion ----------
__global__ void k_zero_edge1(const void* __restrict__ ei, const float* __restrict__ ew,
                             const float* __restrict__ Wxz0, const float* __restrict__ Wxz1,
                             const float* __restrict__ Wxh0, const float* __restrict__ Wxh1,
                             int e, int n, int nbE) {
    int bid = blockIdx.x, tid = threadIdx.x;
    if (bid < NBZ) {
        int i = bid * 256 + tid;
        int4 z = make_int4(0, 0, 0, 0);
        reinterpret_cast<int4*>(g_deg)[i] = z;
        reinterpret_cast<int4*>(g_count)[i] = z;
        reinterpret_cast<int4*>(g_cursor)[i] = z;
        if (bid == 0) {
            if (tid < 64) g_bpref[tid] = 0;
            __shared__ int any;
            if (tid == 0) any = 0;
            __syncthreads();
            if (tid < 128 && ((const int*)ei)[2 * tid + 1] != 0) atomicOr(&any, 1);
            __syncthreads();
            if (tid == 0) g_is64 = (any == 0) ? 1 : 0;
        }
        __syncthreads();
        __threadfence();
        if (tid == 0) atomicAdd(&g_done_a, 1);
    } else if (bid < NBZ + nbE) {
        if (tid == 0) { while (atomicAdd(&g_done_a, 0) < NBZ) {} }
        __syncthreads();
        __threadfence();
        int i = (bid - NBZ) * 256 + tid;
        if (i < e) {
            int s = clampi(load_idx(ei, i), n);
            int d = clampi(load_idx(ei, e + i), n);
            atomicAdd(&g_deg[s], ew[i]);
            atomicAdd(&g_count[d], 1);
        }
    } else {
        // weight conversion: combined Wzh[k][o] -> bf16 hi/lo tiles (row k, col o, stride ST)
        int idx = (bid - NBZ - nbE) * 256 + tid;   // 0..16383
        int k = idx >> 7, o = idx & 127;
        float v;
        if (k < 64) v = (o < 64) ? Wxz0[k * 64 + o] : Wxh0[k * 64 + (o - 64)];
        else        v = (o < 64) ? Wxz1[(k - 64) * 64 + o] : Wxh1[(k - 64) * 64 + (o - 64)];
        __nv_bfloat16 h = __float2bfloat16(v);
        __nv_bfloat16 l = __float2bfloat16(v - __bfloat162float(h));
        g_wbh[k * ST + o] = h;
        g_wbl[k * ST + o] = l;
    }
}

// ---------- B: dinv + scan | edge2 bucket fill ----------
__global__ void k_scan_edge2(const void* __restrict__ ei, const float* __restrict__ ew,
                             int e, int n) {
    int bid = blockIdx.x, tid = threadIdx.x;
    if (bid < NBZ) {
        __shared__ int sh[256];
        __shared__ int s_total;
        int4 c4 = reinterpret_cast<const int4*>(g_count)[bid * 256 + tid];
        float4 d4 = reinterpret_cast<const float4*>(g_deg)[bid * 256 + tid];
        float4 dv;
        dv.x = (d4.x > 0.f) ? rsqrtf(d4.x) : 0.f;
        dv.y = (d4.y > 0.f) ? rsqrtf(d4.y) : 0.f;
        dv.z = (d4.z > 0.f) ? rsqrtf(d4.z) : 0.f;
        dv.w = (d4.w > 0.f) ? rsqrtf(d4.w) : 0.f;
        reinterpret_cast<float4*>(g_dinv)[bid * 256 + tid] = dv;
        int tsum = c4.x + c4.y + c4.z + c4.w;
        sh[tid] = tsum;
        __syncthreads();
        for (int d = 1; d < 256; d <<= 1) {
            int add = (tid >= d) ? sh[tid - d] : 0;
            __syncthreads();
            sh[tid] += add;
            __syncthreads();
        }
        int excl = sh[tid] - tsum;
        int4 o4;
        o4.x = excl;
        o4.y = excl + c4.x;
        o4.z = excl + c4.x + c4.y;
        o4.w = excl + c4.x + c4.y + c4.z;
        reinterpret_cast<int4*>(g_offs)[bid * 256 + tid] = o4;
        if (tid == 255) s_total = sh[255];
        __syncthreads();
        int b2 = bid + 1 + tid;
        if (tid < 64 && b2 < NBZ) atomicAdd(&g_bpref[b2], s_total);
        __threadfence();
        __syncthreads();
        if (tid == 0) atomicAdd(&g_done_b, 1);
    } else {
        if (tid == 0) { while (atomicAdd(&g_done_b, 0) < NBZ) {} }
        __syncthreads();
        __threadfence();
        int i = (bid - NBZ) * 256 + tid;
        if (i < e) {
            int s = clampi(load_idx(ei, i), n);
            int d = clampi(load_idx(ei, e + i), n);
            int pos = g_offs[d] + g_bpref[d >> 10] + atomicAdd(&g_cursor[d], 1);
            pos = clampi(pos, e);
            float c = -g_dinv[s] * ew[i] * g_dinv[d];
            g_pair[pos] = make_int2(s, __float_as_int(c));
        }
    }
}

// ---------- K3: propagation px[dst] = sum coef * x[src], one warp per dst ----------
__global__ void k_prop(const float* __restrict__ x, int n) {
    int gw = (blockIdx.x * blockDim.x + threadIdx.x) >> 5;
    int lane = threadIdx.x & 31;
    if (gw >= n) return;
    int start = g_offs[gw] + g_bpref[gw >> 10];
    int m = g_count[gw];
    float a0 = 0.f, a1 = 0.f;
    if (m > 0) {
        int2 sc = __ldg(&g_pair[start]);
        for (int j = 0; j < m; j++) {
            int2 nxt = __ldg(&g_pair[start + j + 1]);
            const float* xr = x + (size_t)sc.x * 64;
            float c = __int_as_float(sc.y);
            a0 = fmaf(c, __ldg(&xr[lane]), a0);
            a1 = fmaf(c, __ldg(&xr[lane + 32]), a1);
            sc = nxt;
        }
    }
    g_px[(size_t)gw * 64 + lane] = a0;
    g_px[(size_t)gw * 64 + 32 + lane] = a1;
}

// ---------- K4: mma.sync fused kernel, 512 threads ----------
// 128 nodes/block. Warp w: rows (w&7)*16..+16, cols (w>>3)*64..+64.
#define TMF 128
#define SM_AH 0
#define SM_AL (SM_AH + TILE_B)
#define SM_BH (SM_AL + TILE_B)
#define SM_BL (SM_BH + TILE_B)
#define SM_WL (SM_BL + TILE_B)         // 64*32 fp32 = 8192 B
#define SM_BLIN (SM_WL + 8192)         // 128 B
#define SM_BIAS (SM_BLIN + 128)        // 512 B
#define SM_TOT  (SM_BIAS + 512)        // 148096 B
// preact/U overlay on A region after mainloop: 128 rows x 130 fp32 = 66560 B < 2*TILE_B

__global__ __launch_bounds__(512, 1) void k_fused(
    const float* __restrict__ x,
    const float* __restrict__ bxz,  const float* __restrict__ bhz,
    const float* __restrict__ bxh,  const float* __restrict__ bhh,
    const float* __restrict__ Wlin, const float* __restrict__ blin,
    float* __restrict__ out, int n)
{
    extern __shared__ __align__(16) char smem[];
    uint32_t sbase = smem_u32(smem);
    float* sP    = (float*)(smem + SM_AH);     // overlay (after mainloop)
    float* sWl   = (float*)(smem + SM_WL);
    float* sBlin = (float*)(smem + SM_BLIN);
    float* sBias = (float*)(smem + SM_BIAS);

    int tid = threadIdx.x;
    int wid = tid >> 5, lane = tid & 31;
    int node0 = blockIdx.x * TMF;

    if (blockIdx.x == 0 && tid == 0) { g_done_a = 0; g_done_b = 0; }  // replay reset

    // ---- prep A tiles (bf16 hi/lo), float4-vectorized: 8 float4 per thread ----
    for (int idx = tid; idx < TMF * 32; idx += 512) {
        int r = idx >> 5, c4 = idx & 31;
        int node = node0 + r;
        float4 v = make_float4(0.f, 0.f, 0.f, 0.f);
        if (node < n) {
            if (c4 < 16) v = reinterpret_cast<const float4*>(x)[(size_t)node * 16 + c4];
            else         v = reinterpret_cast<const float4*>(g_px)[(size_t)node * 16 + (c4 - 16)];
        }
        __nv_bfloat16 h0 = __float2bfloat16(v.x), h1 = __float2bfloat16(v.y);
        __nv_bfloat16 h2 = __float2bfloat16(v.z), h3 = __float2bfloat16(v.w);
        float l0f = v.x - __bfloat162float(h0), l1f = v.y - __bfloat162float(h1);
        float l2f = v.z - __bfloat162float(h2), l3f = v.w - __bfloat162float(h3);
        uint32_t hw0 = ((uint32_t)__bfloat16_as_ushort(h1) << 16) | __bfloat16_as_ushort(h0);
        uint32_t hw1 = ((uint32_t)__bfloat16_as_ushort(h3) << 16) | __bfloat16_as_ushort(h2);
        uint32_t lw0 = ((uint32_t)__bfloat16_as_ushort(__float2bfloat16(l1f)) << 16)
                     | __bfloat16_as_ushort(__float2bfloat16(l0f));
        uint32_t lw1 = ((uint32_t)__bfloat16_as_ushort(__float2bfloat16(l3f)) << 16)
                     | __bfloat16_as_ushort(__float2bfloat16(l2f));
        uint32_t off = (uint32_t)(r * ST + c4 * 4) * 2;   // 8B-aligned
        *reinterpret_cast<uint2*>(smem + SM_AH + off) = make_uint2(hw0, hw1);
        *reinterpret_cast<uint2*>(smem + SM_AL + off) = make_uint2(lw0, lw1);
    }
    // ---- copy pre-converted B tiles from global (int4) ----
    {
        const int4* src_h = reinterpret_cast<const int4*>(g_wbh);
        const int4* src_l = reinterpret_cast<const int4*>(g_wbl);
        int4* dst_h = reinterpret_cast<int4*>(smem + SM_BH);
        int4* dst_l = reinterpret_cast<int4*>(smem + SM_BL);
        for (int i = tid; i < TILE_B / 16; i += 512) {
            dst_h[i] = src_h[i];
            dst_l[i] = src_l[i];
        }
    }
    for (int idx = tid; idx < 2048; idx += 512) sWl[idx] = Wlin[idx];
    if (tid < 128) sBias[tid] = (tid < 64) ? (bxz[tid] + bhz[tid]) : (bxh[tid - 64] + bhh[tid - 64]);
    if (tid < 32) sBlin[tid] = blin[tid];
    __syncthreads();

    // ---- stage A: warp rows (wid&7)*16, cols (wid>>3)*64 (4 n-pairs of 16) ----
    int mr = wid & 7, nc = wid >> 3;
    int r0 = mr * 16, c0 = nc * 64;
    int qr = lane >> 2, qc = (lane & 3) * 2;
    int lr = lane & 15, lc = (lane >> 4) << 3;
    float acc[8][4];
#pragma unroll
    for (int n8 = 0; n8 < 8; n8++) {
        float b0 = sBias[c0 + n8 * 8 + qc], b1 = sBias[c0 + n8 * 8 + qc + 1];
        acc[n8][0] = b0; acc[n8][1] = b1; acc[n8][2] = b0; acc[n8][3] = b1;
    }
#pragma unroll
    for (int ks = 0; ks < 8; ks++) {
        int k0 = ks * 16;
        uint32_t ah[4], al[4];
        uint32_t aaddr = sbase + SM_AH + (uint32_t)((r0 + lr) * ST + k0 + lc) * 2;
        ldsm4(ah, aaddr);
        ldsm4(al, aaddr + (SM_AL - SM_AH));
#pragma unroll
        for (int np = 0; np < 4; np++) {
            int n0 = c0 + np * 16;
            uint32_t baddr = sbase + SM_BH + (uint32_t)((k0 + lr) * ST + n0 + lc) * 2;
            uint32_t bh[4], bl[4];
            ldsm4t(bh, baddr);
            ldsm4t(bl, baddr + (SM_BL - SM_BH));
            mma16816(acc[2 * np],     ah, bh[0], bh[1]);
            mma16816(acc[2 * np],     ah, bl[0], bl[1]);
            mma16816(acc[2 * np],     al, bh[0], bh[1]);
            mma16816(acc[2 * np + 1], ah, bh[2], bh[3]);
            mma16816(acc[2 * np + 1], ah, bl[2], bl[3]);
            mma16816(acc[2 * np + 1], al, bh[2], bh[3]);
        }
    }
    __syncthreads();   // all tiles read; A/B smem now dead -> overlay sP

    // ---- write preacts (bias included) to sP[128][130] ----
    {
        int r = r0 + qr;
#pragma unroll
        for (int n8 = 0; n8 < 8; n8++) {
            int c = c0 + n8 * 8 + qc;
#pragma unroll
            for (int j = 0; j < 4; j++) {
                int rr = r + ((j >> 1) << 3);
                int cc = c + (j & 1);
                sP[rr * 130 + cc] = acc[n8][j];
            }
        }
    }
    __syncthreads();

    // ---- gate in place: U[r][k] = (1-sigmoid(z))*tanh(h), z=sP[r][k], h=sP[r][k+64] ----
    for (int idx = tid; idx < TMF * 64; idx += 512) {
        int r = idx >> 6, k = idx & 63;
        float zp = sP[r * 130 + k];
        float hp = sP[r * 130 + 64 + k];
        float z = 1.f / (1.f + __expf(-zp));
        sP[r * 130 + k] = (1.f - z) * tanhf(hp);
    }
    __syncthreads();

    // ---- stage B: U(128x64) @ Wlin(64x32) + blin, f32x2; row-normalize ----
    {
        int node = tid >> 2;           // 0..127
        int q = tid & 3;               // out octet: outs q*8..q*8+7
        int ob = q * 8;
        unsigned long long a[4];
#pragma unroll
        for (int m2 = 0; m2 < 4; m2++) a[m2] = packf(sBlin[ob + 2 * m2], sBlin[ob + 2 * m2 + 1]);
#pragma unroll 8
        for (int k = 0; k < 64; k++) {
            unsigned long long up = dupf(sP[node * 130 + k]);
            ulonglong2 w0 = *reinterpret_cast<const ulonglong2*>(&sWl[k * 32 + ob]);
            ulonglong2 w1 = *reinterpret_cast<const ulonglong2*>(&sWl[k * 32 + ob + 4]);
            ffma2(a[0], up, w0.x); ffma2(a[1], up, w0.y);
            ffma2(a[2], up, w1.x); ffma2(a[3], up, w1.y);
        }
        float o[8];
#pragma unroll
        for (int m2 = 0; m2 < 4; m2++) unpackf(a[m2], o[2 * m2], o[2 * m2 + 1]);
        float ss = 0.f;
#pragma unroll
        for (int m2 = 0; m2 < 8; m2++) ss = fmaf(o[m2], o[m2], ss);
        ss += __shfl_xor_sync(0xffffffffu, ss, 1);
        ss += __shfl_xor_sync(0xffffffffu, ss, 2);
        float scale = 1.f / fmaxf(sqrtf(ss), 1e-12f);
        int gnode = node0 + node;
        if (gnode < n) {
            float4 v0 = make_float4(o[0] * scale, o[1] * scale, o[2] * scale, o[3] * scale);
            float4 v1 = make_float4(o[4] * scale, o[5] * scale, o[6] * scale, o[7] * scale);
            reinterpret_cast<float4*>(out)[(size_t)gnode * 8 + q * 2] = v0;
            reinterpret_cast<float4*>(out)[(size_t)gnode * 8 + q * 2 + 1] = v1;
        }
    }
}

extern "C" void kernel_launch(void* const* d_in, const int* in_sizes, int n_in,
                              void* d_out, int out_size) {
    const float* x    = (const float*)d_in[0];
    const void*  ei   = d_in[1];
    const float* ew   = (const float*)d_in[2];
    const float* Wxz0 = (const float*)d_in[3];
    const float* Wxz1 = (const float*)d_in[4];
    const float* bxz  = (const float*)d_in[5];
    const float* bhz  = (const float*)d_in[8];
    const float* Wxh0 = (const float*)d_in[15];
    const float* Wxh1 = (const float*)d_in[16];
    const float* bxh  = (const float*)d_in[17];
    const float* bhh  = (const float*)d_in[20];
    const float* Wlin = (const float*)d_in[21];
    const float* blin = (const float*)d_in[22];
    float* out = (float*)d_out;

    int n = in_sizes[0] / 64;   // 50000
    int e = in_sizes[2];        // 800000

    static int s_attr_done = 0;
    if (!s_attr_done) {
        cudaFuncSetAttribute(k_fused, cudaFuncAttributeMaxDynamicSharedMemorySize, SM_TOT);
        s_attr_done = 1;
    }

    int nbE = (e + 255) / 256;

    k_zero_edge1<<<NBZ + nbE + NWB, 256>>>(ei, ew, Wxz0, Wxz1, Wxh0, Wxh1, e, n, nbE); // #1
    k_scan_edge2<<<NBZ + nbE, 256>>>(ei, ew, e, n);                                    // #2
    k_prop<<<(n * 32 + 255) / 256, 256>>>(x, n);                                       // #3
    k_fused<<<(n + TMF - 1) / TMF, 512, SM_TOT>>>(                                     // #4
        x, bxz, bhz, bxh, bhh, Wlin, blin, out, n);
}

// round 13
// speedup vs baseline: 1.6001x; 1.4607x over previous
#include <cuda_runtime.h>
#include <cuda_bf16.h>
#include <math.h>
#include <stdint.h>

// Problem constants: N=50000 nodes, E=800000 edges, F=64, HID=64, OUT=32
#define MAXN 50176      // 49*1024, divisible by 4
#define MAXE 800008     // +8 pad: prop prefetches one past segment end
#define NBZ 49          // zero/scan blocks (1024 elems each)
#define NWB 64          // weight-conversion blocks appended to k_zero_edge1

#define ST 136          // bf16 tile row stride (verified R11/R12)
#define TILE_B (128 * ST * 2)   // 34816 B per bf16 tile

// ---------- device scratch (no allocations allowed) ----------
__device__ __align__(16) float g_deg[MAXN];
__device__ __align__(16) float g_dinv[MAXN];
__device__ __align__(16) int   g_count[MAXN];
__device__ __align__(16) int   g_cursor[MAXN];
__device__ __align__(16) int   g_offs[MAXN];
__device__ __align__(16) int   g_bpref[64];
__device__ __align__(16) int2  g_pair[MAXE];   // (src, bitcast(coef))
__device__ __align__(16) float g_px[MAXN * 64];
__device__ __align__(16) __nv_bfloat16 g_wbh[128 * ST];  // weight tile hi (ldsm layout)
__device__ __align__(16) __nv_bfloat16 g_wbl[128 * ST];  // weight tile lo
__device__ int g_is64;
__device__ int g_done_a;
__device__ int g_done_b;

__device__ __forceinline__ int load_idx(const void* ei, int pos) {
    if (g_is64) return (int)((const long long*)ei)[pos];
    return ((const int*)ei)[pos];
}
__device__ __forceinline__ int clampi(int v, int n) {
    return ((unsigned)v < (unsigned)n) ? v : 0;
}

// ---------- packed f32x2 helpers ----------
__device__ __forceinline__ void ffma2(unsigned long long& d, unsigned long long a,
                                      unsigned long long b) {
    asm("fma.rn.f32x2 %0, %1, %2, %0;" : "+l"(d) : "l"(a), "l"(b));
}
__device__ __forceinline__ unsigned long long dupf(float f) {
    unsigned long long r;
    asm("mov.b64 %0, {%1, %1};" : "=l"(r) : "f"(f));
    return r;
}
__device__ __forceinline__ unsigned long long packf(float lo, float hi) {
    unsigned long long r;
    asm("mov.b64 %0, {%1, %2};" : "=l"(r) : "f"(lo), "f"(hi));
    return r;
}
__device__ __forceinline__ void unpackf(unsigned long long v, float& lo, float& hi) {
    asm("mov.b64 {%0, %1}, %2;" : "=f"(lo), "=f"(hi) : "l"(v));
}

// ---------- mma.sync helpers ----------
__device__ __forceinline__ uint32_t smem_u32(const void* p) {
    uint32_t a;
    asm("{ .reg .u64 t; cvta.to.shared.u64 t, %1; cvt.u32.u64 %0, t; }" : "=r"(a) : "l"(p));
    return a;
}
__device__ __forceinline__ void ldsm4(uint32_t* r, uint32_t a) {
    asm volatile("ldmatrix.sync.aligned.m8n8.x4.shared.b16 {%0,%1,%2,%3}, [%4];"
        : "=r"(r[0]), "=r"(r[1]), "=r"(r[2]), "=r"(r[3]) : "r"(a));
}
__device__ __forceinline__ void ldsm4t(uint32_t* r, uint32_t a) {
    asm volatile("ldmatrix.sync.aligned.m8n8.x4.trans.shared.b16 {%0,%1,%2,%3}, [%4];"
        : "=r"(r[0]), "=r"(r[1]), "=r"(r[2]), "=r"(r[3]) : "r"(a));
}
// NOTE: not volatile — pure reg->reg; lets ptxas software-pipeline MMAs across LDSMs.
__device__ __forceinline__ void mma16816(float* d, const uint32_t* a, uint32_t b0, uint32_t b1) {
    asm("mma.sync.aligned.m16n8k16.row.col.f32.bf16.bf16.f32 "
        "{%0,%1,%2,%3}, {%4,%5,%6,%7}, {%8,%9}, {%0,%1,%2,%3};"
        : "+f"(d[0]), "+f"(d[1]), "+f"(d[2]), "+f"(d[3])
        : "r"(a[0]), "r"(a[1]), "r"(a[2]), "r"(a[3]), "r"(b0), "r"(b1));
}

// ---------- A: zero+detect | edge1 | weight bf16 conversion ----------
__global__ void k_zero_edge1(const void* __restrict__ ei, const float* __restrict__ ew,
                             const float* __restrict__ Wxz0, const float* __restrict__ Wxz1,
                             const float* __restrict__ Wxh0, const float* __restrict__ Wxh1,
                             int e, int n, int nbE) {
    int bid = blockIdx.x, tid = threadIdx.x;
    if (bid < NBZ) {
        int i = bid * 256 + tid;
        int4 z = make_int4(0, 0, 0, 0);
        reinterpret_cast<int4*>(g_deg)[i] = z;
        reinterpret_cast<int4*>(g_count)[i] = z;
        reinterpret_cast<int4*>(g_cursor)[i] = z;
        if (bid == 0) {
            if (tid < 64) g_bpref[tid] = 0;
            __shared__ int any;
            if (tid == 0) any = 0;
            __syncthreads();
            if (tid < 128 && ((const int*)ei)[2 * tid + 1] != 0) atomicOr(&any, 1);
            __syncthreads();
            if (tid == 0) g_is64 = (any == 0) ? 1 : 0;
        }
        __syncthreads();
        __threadfence();
        if (tid == 0) atomicAdd(&g_done_a, 1);
    } else if (bid < NBZ + nbE) {
        if (tid == 0) { while (atomicAdd(&g_done_a, 0) < NBZ) {} }
        __syncthreads();
        __threadfence();
        int i = (bid - NBZ) * 256 + tid;
        if (i < e) {
            int s = clampi(load_idx(ei, i), n);
            int d = clampi(load_idx(ei, e + i), n);
            atomicAdd(&g_deg[s], ew[i]);
            atomicAdd(&g_count[d], 1);
        }
    } else {
        // weight conversion: combined Wzh[k][o] -> bf16 hi/lo tiles (row k, col o, stride ST)
        int idx = (bid - NBZ - nbE) * 256 + tid;   // 0..16383
        int k = idx >> 7, o = idx & 127;
        float v;
        if (k < 64) v = (o < 64) ? Wxz0[k * 64 + o] : Wxh0[k * 64 + (o - 64)];
        else        v = (o < 64) ? Wxz1[(k - 64) * 64 + o] : Wxh1[(k - 64) * 64 + (o - 64)];
        __nv_bfloat16 h = __float2bfloat16(v);
        __nv_bfloat16 l = __float2bfloat16(v - __bfloat162float(h));
        g_wbh[k * ST + o] = h;
        g_wbl[k * ST + o] = l;
    }
}

// ---------- B: dinv + scan | edge2 bucket fill ----------
__global__ void k_scan_edge2(const void* __restrict__ ei, const float* __restrict__ ew,
                             int e, int n) {
    int bid = blockIdx.x, tid = threadIdx.x;
    if (bid < NBZ) {
        __shared__ int sh[256];
        __shared__ int s_total;
        int4 c4 = reinterpret_cast<const int4*>(g_count)[bid * 256 + tid];
        float4 d4 = reinterpret_cast<const float4*>(g_deg)[bid * 256 + tid];
        float4 dv;
        dv.x = (d4.x > 0.f) ? rsqrtf(d4.x) : 0.f;
        dv.y = (d4.y > 0.f) ? rsqrtf(d4.y) : 0.f;
        dv.z = (d4.z > 0.f) ? rsqrtf(d4.z) : 0.f;
        dv.w = (d4.w > 0.f) ? rsqrtf(d4.w) : 0.f;
        reinterpret_cast<float4*>(g_dinv)[bid * 256 + tid] = dv;
        int tsum = c4.x + c4.y + c4.z + c4.w;
        sh[tid] = tsum;
        __syncthreads();
        for (int d = 1; d < 256; d <<= 1) {
            int add = (tid >= d) ? sh[tid - d] : 0;
            __syncthreads();
            sh[tid] += add;
            __syncthreads();
        }
        int excl = sh[tid] - tsum;
        int4 o4;
        o4.x = excl;
        o4.y = excl + c4.x;
        o4.z = excl + c4.x + c4.y;
        o4.w = excl + c4.x + c4.y + c4.z;
        reinterpret_cast<int4*>(g_offs)[bid * 256 + tid] = o4;
        if (tid == 255) s_total = sh[255];
        __syncthreads();
        int b2 = bid + 1 + tid;
        if (tid < 64 && b2 < NBZ) atomicAdd(&g_bpref[b2], s_total);
        __threadfence();
        __syncthreads();
        if (tid == 0) atomicAdd(&g_done_b, 1);
    } else {
        if (tid == 0) { while (atomicAdd(&g_done_b, 0) < NBZ) {} }
        __syncthreads();
        __threadfence();
        int i = (bid - NBZ) * 256 + tid;
        if (i < e) {
            int s = clampi(load_idx(ei, i), n);
            int d = clampi(load_idx(ei, e + i), n);
            int pos = g_offs[d] + g_bpref[d >> 10] + atomicAdd(&g_cursor[d], 1);
            pos = clampi(pos, e);
            float c = -g_dinv[s] * ew[i] * g_dinv[d];
            g_pair[pos] = make_int2(s, __float_as_int(c));
        }
    }
}

// ---------- K3: propagation px[dst] = sum coef * x[src], one warp per dst ----------
__global__ void k_prop(const float* __restrict__ x, int n) {
    int gw = (blockIdx.x * blockDim.x + threadIdx.x) >> 5;
    int lane = threadIdx.x & 31;
    if (gw >= n) return;
    int start = g_offs[gw] + g_bpref[gw >> 10];
    int m = g_count[gw];
    float a0 = 0.f, a1 = 0.f;
    if (m > 0) {
        int2 sc = __ldg(&g_pair[start]);
        for (int j = 0; j < m; j++) {
            int2 nxt = __ldg(&g_pair[start + j + 1]);
            const float* xr = x + (size_t)sc.x * 64;
            float c = __int_as_float(sc.y);
            a0 = fmaf(c, __ldg(&xr[lane]), a0);
            a1 = fmaf(c, __ldg(&xr[lane + 32]), a1);
            sc = nxt;
        }
    }
    g_px[(size_t)gw * 64 + lane] = a0;
    g_px[(size_t)gw * 64 + 32 + lane] = a1;
}

// ---------- K4: persistent mma.sync fused kernel, 512 threads, 148 blocks ----------
// Each block loops over tiles (128 nodes each). Warp w: rows (w&7)*16, cols (w>>3)*64.
#define TMF 128
#define SM_AH 0
#define SM_AL (SM_AH + TILE_B)
#define SM_BH (SM_AL + TILE_B)
#define SM_BL (SM_BH + TILE_B)
#define SM_WL (SM_BL + TILE_B)         // 64*32 fp32 = 8192 B
#define SM_BLIN (SM_WL + 8192)         // 128 B
#define SM_BIAS (SM_BLIN + 128)        // 512 B
#define SM_TOT  (SM_BIAS + 512)        // 148096 B
// preact/U overlay on A region between mainloop and next fill: 128x130 fp32 = 66560 B < 2*TILE_B

__global__ __launch_bounds__(512, 1) void k_fused(
    const float* __restrict__ x,
    const float* __restrict__ bxz,  const float* __restrict__ bhz,
    const float* __restrict__ bxh,  const float* __restrict__ bhh,
    const float* __restrict__ Wlin, const float* __restrict__ blin,
    float* __restrict__ out, int n, int ntiles)
{
    extern __shared__ __align__(16) char smem[];
    uint32_t sbase = smem_u32(smem);
    float* sP    = (float*)(smem + SM_AH);     // overlay (after mainloop)
    float* sWl   = (float*)(smem + SM_WL);
    float* sBlin = (float*)(smem + SM_BLIN);
    float* sBias = (float*)(smem + SM_BIAS);

    int tid = threadIdx.x;
    int wid = tid >> 5, lane = tid & 31;

    if (blockIdx.x == 0 && tid == 0) { g_done_a = 0; g_done_b = 0; }  // replay reset

    // ---- per-block one-time: weight tiles + Wlin + biases ----
    {
        const int4* src_h = reinterpret_cast<const int4*>(g_wbh);
        const int4* src_l = reinterpret_cast<const int4*>(g_wbl);
        int4* dst_h = reinterpret_cast<int4*>(smem + SM_BH);
        int4* dst_l = reinterpret_cast<int4*>(smem + SM_BL);
        for (int i = tid; i < TILE_B / 16; i += 512) {
            dst_h[i] = src_h[i];
            dst_l[i] = src_l[i];
        }
    }
    for (int idx = tid; idx < 2048; idx += 512) sWl[idx] = Wlin[idx];
    if (tid < 128) sBias[tid] = (tid < 64) ? (bxz[tid] + bhz[tid]) : (bxh[tid - 64] + bhh[tid - 64]);
    if (tid < 32) sBlin[tid] = blin[tid];

    // warp tiling constants (verified mapping)
    int mr = wid & 7, ncw = wid >> 3;
    int r0 = mr * 16, c0 = ncw * 64;
    int qr = lane >> 2, qc = (lane & 3) * 2;
    int lr = lane & 15, lc = (lane >> 4) << 3;

    for (int tile = blockIdx.x; tile < ntiles; tile += gridDim.x) {
        int node0 = tile * TMF;

        // ---- fill A tiles (bf16 hi/lo), float4-vectorized ----
        for (int idx = tid; idx < TMF * 32; idx += 512) {
            int r = idx >> 5, c4 = idx & 31;
            int node = node0 + r;
            float4 v = make_float4(0.f, 0.f, 0.f, 0.f);
            if (node < n) {
                if (c4 < 16) v = reinterpret_cast<const float4*>(x)[(size_t)node * 16 + c4];
                else         v = reinterpret_cast<const float4*>(g_px)[(size_t)node * 16 + (c4 - 16)];
            }
            __nv_bfloat16 h0 = __float2bfloat16(v.x), h1 = __float2bfloat16(v.y);
            __nv_bfloat16 h2 = __float2bfloat16(v.z), h3 = __float2bfloat16(v.w);
            float l0f = v.x - __bfloat162float(h0), l1f = v.y - __bfloat162float(h1);
            float l2f = v.z - __bfloat162float(h2), l3f = v.w - __bfloat162float(h3);
            uint32_t hw0 = ((uint32_t)__bfloat16_as_ushort(h1) << 16) | __bfloat16_as_ushort(h0);
            uint32_t hw1 = ((uint32_t)__bfloat16_as_ushort(h3) << 16) | __bfloat16_as_ushort(h2);
            uint32_t lw0 = ((uint32_t)__bfloat16_as_ushort(__float2bfloat16(l1f)) << 16)
                         | __bfloat16_as_ushort(__float2bfloat16(l0f));
            uint32_t lw1 = ((uint32_t)__bfloat16_as_ushort(__float2bfloat16(l3f)) << 16)
                         | __bfloat16_as_ushort(__float2bfloat16(l2f));
            uint32_t off = (uint32_t)(r * ST + c4 * 4) * 2;
            *reinterpret_cast<uint2*>(smem + SM_AH + off) = make_uint2(hw0, hw1);
            *reinterpret_cast<uint2*>(smem + SM_AL + off) = make_uint2(lw0, lw1);
        }
        __syncthreads();   // A ready (and B, on first iteration)

        // ---- stage A mainloop: batched LDSM issue (A + 2 np-tiles), then 12 MMAs ----
        float acc[8][4];
#pragma unroll
        for (int n8 = 0; n8 < 8; n8++) {
            float b0 = sBias[c0 + n8 * 8 + qc], b1 = sBias[c0 + n8 * 8 + qc + 1];
            acc[n8][0] = b0; acc[n8][1] = b1; acc[n8][2] = b0; acc[n8][3] = b1;
        }
#pragma unroll
        for (int ks = 0; ks < 8; ks++) {
            int k0 = ks * 16;
            uint32_t ah[4], al[4];
            uint32_t aaddr = sbase + SM_AH + (uint32_t)((r0 + lr) * ST + k0 + lc) * 2;
            ldsm4(ah, aaddr);
            ldsm4(al, aaddr + (SM_AL - SM_AH));
#pragma unroll
            for (int npp = 0; npp < 2; npp++) {
                int np0 = npp * 2;
                uint32_t b0addr = sbase + SM_BH
                    + (uint32_t)((k0 + lr) * ST + c0 + np0 * 16 + lc) * 2;
                uint32_t b1addr = b0addr + 32;   // +16 bf16 cols
                uint32_t bh0[4], bl0[4], bh1[4], bl1[4];
                ldsm4t(bh0, b0addr);
                ldsm4t(bl0, b0addr + (SM_BL - SM_BH));
                ldsm4t(bh1, b1addr);
                ldsm4t(bl1, b1addr + (SM_BL - SM_BH));
                mma16816(acc[2 * np0],     ah, bh0[0], bh0[1]);
                mma16816(acc[2 * np0],     ah, bl0[0], bl0[1]);
                mma16816(acc[2 * np0],     al, bh0[0], bh0[1]);
                mma16816(acc[2 * np0 + 1], ah, bh0[2], bh0[3]);
                mma16816(acc[2 * np0 + 1], ah, bl0[2], bl0[3]);
                mma16816(acc[2 * np0 + 1], al, bh0[2], bh0[3]);
                mma16816(acc[2 * np0 + 2], ah, bh1[0], bh1[1]);
                mma16816(acc[2 * np0 + 2], ah, bl1[0], bl1[1]);
                mma16816(acc[2 * np0 + 2], al, bh1[0], bh1[1]);
                mma16816(acc[2 * np0 + 3], ah, bh1[2], bh1[3]);
                mma16816(acc[2 * np0 + 3], ah, bl1[2], bl1[3]);
                mma16816(acc[2 * np0 + 3], al, bh1[2], bh1[3]);
            }
        }
        __syncthreads();   // A region dead -> overlay sP

        // ---- write preacts (bias included) to sP[128][130] ----
        {
            int r = r0 + qr;
#pragma unroll
            for (int n8 = 0; n8 < 8; n8++) {
                int c = c0 + n8 * 8 + qc;
#pragma unroll
                for (int j = 0; j < 4; j++) {
                    int rr = r + ((j >> 1) << 3);
                    int cc = c + (j & 1);
                    sP[rr * 130 + cc] = acc[n8][j];
                }
            }
        }
        __syncthreads();

        // ---- gate in place ----
        for (int idx = tid; idx < TMF * 64; idx += 512) {
            int r = idx >> 6, k = idx & 63;
            float zp = sP[r * 130 + k];
            float hp = sP[r * 130 + 64 + k];
            float z = 1.f / (1.f + __expf(-zp));
            sP[r * 130 + k] = (1.f - z) * tanhf(hp);
        }
        __syncthreads();

        // ---- stage B: U(128x64) @ Wlin(64x32) + blin, f32x2; row-normalize ----
        {
            int node = tid >> 2;
            int q = tid & 3;
            int ob = q * 8;
            unsigned long long a[4];
#pragma unroll
            for (int m2 = 0; m2 < 4; m2++)
                a[m2] = packf(sBlin[ob + 2 * m2], sBlin[ob + 2 * m2 + 1]);
#pragma unroll 8
            for (int k = 0; k < 64; k++) {
                unsigned long long up = dupf(sP[node * 130 + k]);
                ulonglong2 w0 = *reinterpret_cast<const ulonglong2*>(&sWl[k * 32 + ob]);
                ulonglong2 w1 = *reinterpret_cast<const ulonglong2*>(&sWl[k * 32 + ob + 4]);
                ffma2(a[0], up, w0.x); ffma2(a[1], up, w0.y);
                ffma2(a[2], up, w1.x); ffma2(a[3], up, w1.y);
            }
            float o[8];
#pragma unroll
            for (int m2 = 0; m2 < 4; m2++) unpackf(a[m2], o[2 * m2], o[2 * m2 + 1]);
            float ss = 0.f;
#pragma unroll
            for (int m2 = 0; m2 < 8; m2++) ss = fmaf(o[m2], o[m2], ss);
            ss += __shfl_xor_sync(0xffffffffu, ss, 1);
            ss += __shfl_xor_sync(0xffffffffu, ss, 2);
            float scale = 1.f / fmaxf(sqrtf(ss), 1e-12f);
            int gnode = node0 + node;
            if (gnode < n) {
                float4 v0 = make_float4(o[0] * scale, o[1] * scale, o[2] * scale, o[3] * scale);
                float4 v1 = make_float4(o[4] * scale, o[5] * scale, o[6] * scale, o[7] * scale);
                reinterpret_cast<float4*>(out)[(size_t)gnode * 8 + q * 2] = v0;
                reinterpret_cast<float4*>(out)[(size_t)gnode * 8 + q * 2 + 1] = v1;
            }
        }
        __syncthreads();   // sP (A region) fully consumed before next tile's fill
    }
}

extern "C" void kernel_launch(void* const* d_in, const int* in_sizes, int n_in,
                              void* d_out, int out_size) {
    const float* x    = (const float*)d_in[0];
    const void*  ei   = d_in[1];
    const float* ew   = (const float*)d_in[2];
    const float* Wxz0 = (const float*)d_in[3];
    const float* Wxz1 = (const float*)d_in[4];
    const float* bxz  = (const float*)d_in[5];
    const float* bhz  = (const float*)d_in[8];
    const float* Wxh0 = (const float*)d_in[15];
    const float* Wxh1 = (const float*)d_in[16];
    const float* bxh  = (const float*)d_in[17];
    const float* bhh  = (const float*)d_in[20];
    const float* Wlin = (const float*)d_in[21];
    const float* blin = (const float*)d_in[22];
    float* out = (float*)d_out;

    int n = in_sizes[0] / 64;   // 50000
    int e = in_sizes[2];        // 800000

    static int s_attr_done = 0;
    if (!s_attr_done) {
        cudaFuncSetAttribute(k_fused, cudaFuncAttributeMaxDynamicSharedMemorySize, SM_TOT);
        s_attr_done = 1;
    }

    int nbE = (e + 255) / 256;
    int ntiles = (n + TMF - 1) / TMF;

    k_zero_edge1<<<NBZ + nbE + NWB, 256>>>(ei, ew, Wxz0, Wxz1, Wxh0, Wxh1, e, n, nbE); // #1
    k_scan_edge2<<<NBZ + nbE, 256>>>(ei, ew, e, n);                                    // #2
    k_prop<<<(n * 32 + 255) / 256, 256>>>(x, n);                                       // #3
    k_fused<<<148, 512, SM_TOT>>>(                                                     // #4
        x, bxz, bhz, bxh, bhh, Wlin, blin, out, n, ntiles);
}